// round 3
// baseline (speedup 1.0000x reference)
#include <cuda_runtime.h>
#include <cstdint>

// Problem constants
#define NB   64          // batch
#define CC   256         // channels
#define HH   28
#define WW   28
#define PIX  (HH*WW)                 // 784
#define NPIX (NB*PIX)                // 50176
#define TOT  (NB*CC*PIX)             // 12,845,056
#define CW   8                       // 256 channels / 32 bits
#define TH   4                       // rows per conv block

// ---------------- scratch (device globals; no allocation allowed) --------
__device__ uint32_t g_bits[NB*PIX*CW];            // packed activation signs
__device__ uint32_t g_wb[2][CC*72];               // packed weight signs: [oc][tap][word]
__device__ int      g_pw[2][CC*9];                // popcount of each weight tap
__device__ short    g_y[TOT];                     // integer conv output
__device__ float    g_out1[TOT];                  // stage-1 output (residual for stage 2)
__device__ int                g_sum[2][CC];
__device__ unsigned long long g_sq [2][CC];
__device__ float    g_scale[2][CC], g_shift[2][CC];

// ---------------- zero the stats accumulators ----------------------------
__global__ void zero_kernel() {
    int t = threadIdx.x;            // 256 threads
    g_sum[0][t] = 0; g_sum[1][t] = 0;
    g_sq [0][t] = 0; g_sq [1][t] = 0;
}

// ---------------- pack weights: sign bits + per-tap popcounts ------------
// w layout OIHW: idx = oc*2304 + ic*9 + (ky*3+kx). block = (32,9), one block per (oc,set)
__global__ void pack_w_kernel(const float* __restrict__ w1,
                              const float* __restrict__ w2) {
    int oc    = blockIdx.x;
    int which = blockIdx.y;
    const float* w = which ? w2 : w1;
    int tap  = threadIdx.y;          // 0..8
    int lane = threadIdx.x;          // 0..31
    int pwt = 0;
    #pragma unroll
    for (int j = 0; j < CW; j++) {
        float v = w[oc*2304 + (j*32 + lane)*9 + tap];
        unsigned word = __ballot_sync(0xffffffffu, v > 0.0f);
        if (lane == 0) g_wb[which][oc*72 + tap*8 + j] = word;
        pwt += __popc(word);
    }
    if (lane == 0) g_pw[which][oc*9 + tap] = pwt;
}

// ---------------- pack activation signs -----------------------------------
// block per (h, n); 256 threads. src is NCHW fp32. Writes g_bits[n][h][w][cw].
__global__ void pack_sign_kernel(const float* __restrict__ src, int from_g) {
    __shared__ unsigned char s[CC*WW];      // 7168 sign bytes
    int h = blockIdx.x, n = blockIdx.y;
    const float* sp = from_g ? g_out1 : src;
    int basen = n * (CC*PIX);
    #pragma unroll
    for (int k = 0; k < 28; k++) {
        int e = threadIdx.x + k*256;         // e = c*28 + w
        int c = e / 28, w = e - c*28;
        float v = sp[basen + c*PIX + h*WW + w];
        s[e] = (v > 0.0f) ? 1 : 0;
    }
    __syncthreads();
    int warp = threadIdx.x >> 5, lane = threadIdx.x & 31;   // warp = channel word
    #pragma unroll
    for (int w = 0; w < 28; w++) {
        unsigned pred = s[(warp*32 + lane)*28 + w];
        unsigned word = __ballot_sync(0xffffffffu, pred != 0);
        if (lane == w) g_bits[n*(PIX*CW) + (h*WW + w)*CW + warp] = word;
    }
}

// ---------------- XNOR-popcount conv + channel-stat accumulation ---------
// block = 128 threads, handles (n, 4 rows). Weights+pw+act tile in smem,
// per-pixel act bits in registers, loop over 256 output channels.
#define SMEM_W  (CC*72)             // 18432 u32
#define SMEM_PW (CC*9)              // 2304  u32
#define SMEM_A  (6*WW*CW)           // 1344  u32
#define SMEM_U32 (SMEM_W + SMEM_PW + SMEM_A)

__global__ void __launch_bounds__(128) conv_kernel(int which) {
    extern __shared__ uint32_t sh[];
    uint32_t* s_w  = sh;
    int*      s_pw = (int*)(sh + SMEM_W);
    uint32_t* s_a  = sh + SMEM_W + SMEM_PW;

    const int n   = blockIdx.y;
    const int h0  = blockIdx.x * TH;
    const int tid = threadIdx.x;

    const uint32_t* wb = g_wb[which];
    const int*      pw = g_pw[which];

    for (int i = tid; i < SMEM_W;  i += 128) s_w[i]  = wb[i];
    for (int i = tid; i < SMEM_PW; i += 128) s_pw[i] = pw[i];
    // activation tile: rows h0-1 .. h0+4 (zero outside image)
    for (int i = tid; i < SMEM_A; i += 128) {
        int rr  = i / (WW*CW);
        int rem = i - rr*(WW*CW);
        int hh  = h0 - 1 + rr;
        s_a[i] = (hh >= 0 && hh < HH) ? g_bits[n*(PIX*CW) + hh*(WW*CW) + rem] : 0u;
    }
    __syncthreads();

    const bool active = (tid < TH*WW);        // 112 workers
    const int p = active ? tid : (TH*WW - 1);
    const int r = p / WW;
    const int w = p - r*WW;
    const int h = h0 + r;

    // per-pixel activation bits in registers (zero for out-of-image columns)
    uint32_t a[72];
    #pragma unroll
    for (int ky = 0; ky < 3; ky++)
        #pragma unroll
        for (int kx = 0; kx < 3; kx++) {
            int ww = w + kx - 1;
            bool v = (ww >= 0) && (ww < WW);
            int base = ((r + ky)*WW + (v ? ww : 0))*CW;
            #pragma unroll
            for (int j = 0; j < CW; j++)
                a[(ky*3+kx)*CW + j] = v ? s_a[base + j] : 0u;
        }

    const int inv_row = (h == 0) ? 0 : ((h == HH-1) ? 2 : -1);
    const int inv_col = (w == 0) ? 0 : ((w == WW-1) ? 2 : -1);
    const int nv = ((inv_row < 0) ? 3 : 2) * ((inv_col < 0) ? 3 : 2);
    const int base256 = CC * nv;

    short* yout = g_y + n*(CC*PIX) + h0*WW + p;   // + oc*PIX per channel
    int* gsum = g_sum[which];
    unsigned long long* gsq = g_sq[which];
    const int lane = tid & 31;

    const uint32_t* wrow = s_w;
    for (int oc = 0; oc < CC; oc++, wrow += 72) {
        int a0 = 0, a1 = 0, a2 = 0, a3 = 0;
        #pragma unroll
        for (int t = 0; t < 18; t++) {
            a0 += __popc(a[t*4+0] ^ wrow[t*4+0]);
            a1 += __popc(a[t*4+1] ^ wrow[t*4+1]);
            a2 += __popc(a[t*4+2] ^ wrow[t*4+2]);
            a3 += __popc(a[t*4+3] ^ wrow[t*4+3]);
        }
        int acc = (a0 + a1) + (a2 + a3);

        int corr = 0;
        const int* pwo = s_pw + oc*9;
        if (inv_row >= 0)
            corr += pwo[inv_row*3+0] + pwo[inv_row*3+1] + pwo[inv_row*3+2];
        if (inv_col >= 0)
            corr += pwo[inv_col] + pwo[3+inv_col] + pwo[6+inv_col];
        if (inv_row >= 0 && inv_col >= 0)
            corr -= pwo[inv_row*3 + inv_col];

        int y = base256 - 2*acc + 2*corr;
        if (!active) y = 0;
        if (active) yout[oc*PIX] = (short)y;

        int s1 = __reduce_add_sync(0xffffffffu, y);
        int s2 = __reduce_add_sync(0xffffffffu, y*y);   // <= 32*2304^2 < 2^31
        if (lane == 0) {
            atomicAdd(&gsum[oc], s1);
            atomicAdd(&gsq[oc], (unsigned long long)(unsigned int)s2);
        }
    }
}

// ---------------- BN statistics -> scale/shift (exact integer sums) -------
__global__ void stats_kernel(int which, const float* __restrict__ gamma,
                             const float* __restrict__ beta) {
    int c = threadIdx.x;                       // 256 threads
    double m   = (double)g_sum[which][c] / (double)NPIX;
    double ex2 = (double)g_sq [which][c] / (double)NPIX;
    double var = ex2 - m*m;
    double inv = rsqrt(var + 1e-5);
    double gs  = (double)gamma[c] * inv;
    g_scale[which][c] = (float)gs;
    g_shift[which][c] = (float)((double)beta[c] - m * gs);
}

// ---------------- BN apply + residual + hardtanh ---------------------------
__global__ void __launch_bounds__(256) bnres_kernel(int which,
                                                    const float* __restrict__ res_in,
                                                    float* __restrict__ dst_out) {
    int idx = blockIdx.x * 256 + threadIdx.x;      // grid sized exactly to TOT
    int c = (idx / PIX) & (CC - 1);
    float v = fmaf((float)g_y[idx], g_scale[which][c], g_shift[which][c]);
    const float* res = (which == 0) ? res_in : g_out1;
    v += res[idx];
    v = fminf(1.0f, fmaxf(-1.0f, v));
    if (which == 0) g_out1[idx] = v;
    else            dst_out[idx] = v;
}

// ---------------- launcher -------------------------------------------------
extern "C" void kernel_launch(void* const* d_in, const int* in_sizes, int n_in,
                              void* d_out, int out_size) {
    const float* x      = (const float*)d_in[0];
    const float* w1     = (const float*)d_in[1];
    const float* gamma1 = (const float*)d_in[2];
    const float* beta1  = (const float*)d_in[3];
    const float* w2     = (const float*)d_in[4];
    const float* gamma2 = (const float*)d_in[5];
    const float* beta2  = (const float*)d_in[6];
    float* out = (float*)d_out;

    constexpr int SMEM_BYTES = SMEM_U32 * 4;       // 88,320 B
    cudaFuncSetAttribute(conv_kernel,
                         cudaFuncAttributeMaxDynamicSharedMemorySize, SMEM_BYTES);

    zero_kernel<<<1, 256>>>();
    pack_w_kernel<<<dim3(CC, 2), dim3(32, 9)>>>(w1, w2);

    // stage 1
    pack_sign_kernel<<<dim3(HH, NB), 256>>>(x, 0);
    conv_kernel<<<dim3(HH/TH, NB), 128, SMEM_BYTES>>>(0);
    stats_kernel<<<1, 256>>>(0, gamma1, beta1);
    bnres_kernel<<<TOT/256, 256>>>(0, x, nullptr);

    // stage 2
    pack_sign_kernel<<<dim3(HH, NB), 256>>>(nullptr, 1);
    conv_kernel<<<dim3(HH/TH, NB), 128, SMEM_BYTES>>>(1);
    stats_kernel<<<1, 256>>>(1, gamma2, beta2);
    bnres_kernel<<<TOT/256, 256>>>(1, nullptr, out);
}

// round 4
// speedup vs baseline: 1.5247x; 1.5247x over previous
#include <cuda_runtime.h>
#include <cstdint>

// Problem constants
#define NB   64          // batch
#define CC   256         // channels
#define HH   28
#define WW   28
#define PIX  (HH*WW)                 // 784
#define NPIX (NB*PIX)                // 50176
#define TOT  (NB*CC*PIX)             // 12,845,056
#define CW   8                       // 256 channels / 32 bits
#define TH   4                       // rows per conv block
#define OCCH 64                      // output channels per block (oc chunk)
#define NCH  (CC/OCCH)               // 4 chunks

// ---------------- scratch (device globals; no allocation allowed) --------
__device__ uint32_t g_bits[NB*PIX*CW];            // packed activation signs
__device__ uint32_t g_wb[2][CC*72];               // packed weight signs: [oc][tap][word]
__device__ int      g_pw[2][CC*9];                // popcount of each weight tap
__device__ short    g_y[TOT];                     // integer conv output
__device__ float    g_out1[TOT];                  // stage-1 output (residual for stage 2)
__device__ int                g_sum[2][CC];
__device__ unsigned long long g_sq [2][CC];
__device__ float    g_scale[2][CC], g_shift[2][CC];

// ---------------- zero the stats accumulators ----------------------------
__global__ void zero_kernel() {
    int t = threadIdx.x;            // 256 threads
    g_sum[0][t] = 0; g_sum[1][t] = 0;
    g_sq [0][t] = 0; g_sq [1][t] = 0;
}

// ---------------- pack weights: sign bits + per-tap popcounts ------------
// w layout OIHW: idx = oc*2304 + ic*9 + (ky*3+kx). block = (32,9), one block per (oc,set)
__global__ void pack_w_kernel(const float* __restrict__ w1,
                              const float* __restrict__ w2) {
    int oc    = blockIdx.x;
    int which = blockIdx.y;
    const float* w = which ? w2 : w1;
    int tap  = threadIdx.y;          // 0..8
    int lane = threadIdx.x;          // 0..31
    int pwt = 0;
    #pragma unroll
    for (int j = 0; j < CW; j++) {
        float v = w[oc*2304 + (j*32 + lane)*9 + tap];
        unsigned word = __ballot_sync(0xffffffffu, v > 0.0f);
        if (lane == 0) g_wb[which][oc*72 + tap*8 + j] = word;
        pwt += __popc(word);
    }
    if (lane == 0) g_pw[which][oc*9 + tap] = pwt;
}

// ---------------- pack activation signs -----------------------------------
// block per (h, n); 256 threads. src is NCHW fp32. Writes g_bits[n][h][w][cw].
__global__ void pack_sign_kernel(const float* __restrict__ src, int from_g) {
    __shared__ unsigned char s[CC*WW];      // 7168 sign bytes
    int h = blockIdx.x, n = blockIdx.y;
    const float* sp = from_g ? g_out1 : src;
    int basen = n * (CC*PIX);
    #pragma unroll
    for (int k = 0; k < 28; k++) {
        int e = threadIdx.x + k*256;         // e = c*28 + w
        int c = e / 28, w = e - c*28;
        float v = sp[basen + c*PIX + h*WW + w];
        s[e] = (v > 0.0f) ? 1 : 0;
    }
    __syncthreads();
    int warp = threadIdx.x >> 5, lane = threadIdx.x & 31;   // warp = channel word
    #pragma unroll
    for (int w = 0; w < 28; w++) {
        unsigned pred = s[(warp*32 + lane)*28 + w];
        unsigned word = __ballot_sync(0xffffffffu, pred != 0);
        if (lane == w) g_bits[n*(PIX*CW) + (h*WW + w)*CW + warp] = word;
    }
}

// ---------------- XNOR-popcount conv + channel-stat accumulation ---------
// block = 128 threads, handles (n, 4 rows, 64-oc chunk). Weights+pw+act tile
// in smem, per-pixel act bits in registers, loop over 64 output channels.
#define SMEM_W  (OCCH*72)           // 4608 u32
#define SMEM_PW (OCCH*9)            // 576  u32
#define SMEM_A  (6*WW*CW)           // 1344 u32
#define SMEM_U32 (SMEM_W + SMEM_PW + SMEM_A)

__global__ void __launch_bounds__(128) conv_kernel(int which) {
    extern __shared__ uint32_t sh[];
    uint32_t* s_w  = sh;
    int*      s_pw = (int*)(sh + SMEM_W);
    uint32_t* s_a  = sh + SMEM_W + SMEM_PW;

    const int n   = blockIdx.y;
    const int h0  = blockIdx.x * TH;
    const int oc0 = blockIdx.z * OCCH;
    const int tid = threadIdx.x;

    const uint32_t* wb = g_wb[which] + oc0*72;
    const int*      pw = g_pw[which] + oc0*9;

    for (int i = tid; i < SMEM_W;  i += 128) s_w[i]  = wb[i];
    for (int i = tid; i < SMEM_PW; i += 128) s_pw[i] = pw[i];
    // activation tile: rows h0-1 .. h0+4 (zero outside image)
    for (int i = tid; i < SMEM_A; i += 128) {
        int rr  = i / (WW*CW);
        int rem = i - rr*(WW*CW);
        int hh  = h0 - 1 + rr;
        s_a[i] = (hh >= 0 && hh < HH) ? g_bits[n*(PIX*CW) + hh*(WW*CW) + rem] : 0u;
    }
    __syncthreads();

    const bool active = (tid < TH*WW);        // 112 workers
    const int p = active ? tid : (TH*WW - 1);
    const int r = p / WW;
    const int w = p - r*WW;
    const int h = h0 + r;

    // per-pixel activation bits in registers (zero for out-of-image columns)
    uint32_t a[72];
    #pragma unroll
    for (int ky = 0; ky < 3; ky++)
        #pragma unroll
        for (int kx = 0; kx < 3; kx++) {
            int ww = w + kx - 1;
            bool v = (ww >= 0) && (ww < WW);
            int base = ((r + ky)*WW + (v ? ww : 0))*CW;
            #pragma unroll
            for (int j = 0; j < CW; j++)
                a[(ky*3+kx)*CW + j] = v ? s_a[base + j] : 0u;
        }

    const int inv_row = (h == 0) ? 0 : ((h == HH-1) ? 2 : -1);
    const int inv_col = (w == 0) ? 0 : ((w == WW-1) ? 2 : -1);
    const int nv = ((inv_row < 0) ? 3 : 2) * ((inv_col < 0) ? 3 : 2);
    const int base256 = CC * nv;

    short* yout = g_y + n*(CC*PIX) + (size_t)oc0*PIX + h0*WW + p; // + oc*PIX per channel
    int* gsum = g_sum[which] + oc0;
    unsigned long long* gsq = g_sq[which] + oc0;
    const int lane = tid & 31;

    const uint32_t* wrow = s_w;
    for (int oc = 0; oc < OCCH; oc++, wrow += 72) {
        int a0 = 0, a1 = 0, a2 = 0, a3 = 0;
        #pragma unroll
        for (int t = 0; t < 18; t++) {
            a0 += __popc(a[t*4+0] ^ wrow[t*4+0]);
            a1 += __popc(a[t*4+1] ^ wrow[t*4+1]);
            a2 += __popc(a[t*4+2] ^ wrow[t*4+2]);
            a3 += __popc(a[t*4+3] ^ wrow[t*4+3]);
        }
        int acc = (a0 + a1) + (a2 + a3);

        int corr = 0;
        const int* pwo = s_pw + oc*9;
        if (inv_row >= 0)
            corr += pwo[inv_row*3+0] + pwo[inv_row*3+1] + pwo[inv_row*3+2];
        if (inv_col >= 0)
            corr += pwo[inv_col] + pwo[3+inv_col] + pwo[6+inv_col];
        if (inv_row >= 0 && inv_col >= 0)
            corr -= pwo[inv_row*3 + inv_col];

        int y = base256 - 2*acc + 2*corr;
        if (!active) y = 0;
        if (active) yout[oc*PIX] = (short)y;

        int s1 = __reduce_add_sync(0xffffffffu, y);
        int s2 = __reduce_add_sync(0xffffffffu, y*y);   // <= 32*2304^2 < 2^31
        if (lane == 0) {
            atomicAdd(&gsum[oc], s1);
            atomicAdd(&gsq[oc], (unsigned long long)(unsigned int)s2);
        }
    }
}

// ---------------- BN statistics -> scale/shift (exact integer sums) -------
__global__ void stats_kernel(int which, const float* __restrict__ gamma,
                             const float* __restrict__ beta) {
    int c = threadIdx.x;                       // 256 threads
    double m   = (double)g_sum[which][c] / (double)NPIX;
    double ex2 = (double)g_sq [which][c] / (double)NPIX;
    double var = ex2 - m*m;
    double inv = rsqrt(var + 1e-5);
    double gs  = (double)gamma[c] * inv;
    g_scale[which][c] = (float)gs;
    g_shift[which][c] = (float)((double)beta[c] - m * gs);
}

// ---------------- BN apply + residual + hardtanh ---------------------------
__global__ void __launch_bounds__(256) bnres_kernel(int which,
                                                    const float* __restrict__ res_in,
                                                    float* __restrict__ dst_out) {
    int idx = blockIdx.x * 256 + threadIdx.x;      // grid sized exactly to TOT
    int c = (idx / PIX) & (CC - 1);
    float v = fmaf((float)g_y[idx], g_scale[which][c], g_shift[which][c]);
    const float* res = (which == 0) ? res_in : g_out1;
    v += res[idx];
    v = fminf(1.0f, fmaxf(-1.0f, v));
    if (which == 0) g_out1[idx] = v;
    else            dst_out[idx] = v;
}

// ---------------- launcher -------------------------------------------------
extern "C" void kernel_launch(void* const* d_in, const int* in_sizes, int n_in,
                              void* d_out, int out_size) {
    const float* x      = (const float*)d_in[0];
    const float* w1     = (const float*)d_in[1];
    const float* gamma1 = (const float*)d_in[2];
    const float* beta1  = (const float*)d_in[3];
    const float* w2     = (const float*)d_in[4];
    const float* gamma2 = (const float*)d_in[5];
    const float* beta2  = (const float*)d_in[6];
    float* out = (float*)d_out;

    constexpr int SMEM_BYTES = SMEM_U32 * 4;       // 26,112 B

    zero_kernel<<<1, 256>>>();
    pack_w_kernel<<<dim3(CC, 2), dim3(32, 9)>>>(w1, w2);

    // stage 1
    pack_sign_kernel<<<dim3(HH, NB), 256>>>(x, 0);
    conv_kernel<<<dim3(HH/TH, NB, NCH), 128, SMEM_BYTES>>>(0);
    stats_kernel<<<1, 256>>>(0, gamma1, beta1);
    bnres_kernel<<<TOT/256, 256>>>(0, x, nullptr);

    // stage 2
    pack_sign_kernel<<<dim3(HH, NB), 256>>>(nullptr, 1);
    conv_kernel<<<dim3(HH/TH, NB, NCH), 128, SMEM_BYTES>>>(1);
    stats_kernel<<<1, 256>>>(1, gamma2, beta2);
    bnres_kernel<<<TOT/256, 256>>>(1, nullptr, out);
}

// round 5
// speedup vs baseline: 1.5273x; 1.0017x over previous
#include <cuda_runtime.h>
#include <cstdint>

// Problem constants
#define NB   64          // batch
#define CC   256         // channels
#define HH   28
#define WW   28
#define PIX  (HH*WW)                 // 784
#define NPIX (NB*PIX)                // 50176
#define TOT  (NB*CC*PIX)             // 12,845,056
#define CW   8                       // 256 channels / 32 bits
#define TH   4                       // rows per conv block
#define OCCH 64                      // output channels per block (oc chunk)
#define NCH  (CC/OCCH)               // 4 chunks

// ---------------- scratch (device globals; no allocation allowed) --------
__device__ uint32_t g_bits[NB*PIX*CW];            // packed activation signs
__device__ uint32_t g_wb[2][CC*72];               // packed weight signs: [oc][tap][word]
__device__ int      g_pw[2][CC*9];                // popcount of each weight tap
__device__ short    g_y[TOT];                     // integer conv output
__device__ float    g_out1[TOT];                  // stage-1 output (residual for stage 2)
__device__ int                g_sum[2][CC];
__device__ unsigned long long g_sq [2][CC];
__device__ float    g_scale[2][CC], g_shift[2][CC];

// ---------------- zero the stats accumulators ----------------------------
__global__ void zero_kernel() {
    int t = threadIdx.x;            // 256 threads
    g_sum[0][t] = 0; g_sum[1][t] = 0;
    g_sq [0][t] = 0; g_sq [1][t] = 0;
}

// ---------------- pack weights: sign bits + per-tap popcounts ------------
// w layout OIHW: idx = oc*2304 + ic*9 + (ky*3+kx). block = (32,9), one block per (oc,set)
__global__ void pack_w_kernel(const float* __restrict__ w1,
                              const float* __restrict__ w2) {
    int oc    = blockIdx.x;
    int which = blockIdx.y;
    const float* w = which ? w2 : w1;
    int tap  = threadIdx.y;          // 0..8
    int lane = threadIdx.x;          // 0..31
    int pwt = 0;
    #pragma unroll
    for (int j = 0; j < CW; j++) {
        float v = w[oc*2304 + (j*32 + lane)*9 + tap];
        unsigned word = __ballot_sync(0xffffffffu, v > 0.0f);
        if (lane == 0) g_wb[which][oc*72 + tap*8 + j] = word;
        pwt += __popc(word);
    }
    if (lane == 0) g_pw[which][oc*9 + tap] = pwt;
}

// ---------------- pack activation signs -----------------------------------
// block per (h, n); 256 threads. src is NCHW fp32. Writes g_bits[n][h][w][cw].
__global__ void pack_sign_kernel(const float* __restrict__ src, int from_g) {
    __shared__ unsigned char s[CC*WW];      // 7168 sign bytes
    int h = blockIdx.x, n = blockIdx.y;
    const float* sp = from_g ? g_out1 : src;
    int basen = n * (CC*PIX);
    #pragma unroll
    for (int k = 0; k < 28; k++) {
        int e = threadIdx.x + k*256;         // e = c*28 + w
        int c = e / 28, w = e - c*28;
        float v = sp[basen + c*PIX + h*WW + w];
        s[e] = (v > 0.0f) ? 1 : 0;
    }
    __syncthreads();
    int warp = threadIdx.x >> 5, lane = threadIdx.x & 31;   // warp = channel word
    #pragma unroll
    for (int w = 0; w < 28; w++) {
        unsigned pred = s[(warp*32 + lane)*28 + w];
        unsigned word = __ballot_sync(0xffffffffu, pred != 0);
        if (lane == w) g_bits[n*(PIX*CW) + (h*WW + w)*CW + warp] = word;
    }
}

// ---------------- XNOR-popcount conv + channel-stat accumulation ---------
// block = 128 threads, handles (n, 4 rows, 64-oc chunk). Weights+pw+act tile
// in smem, per-pixel act bits in registers, loop over 64 output channels.
#define SMEM_W  (OCCH*72)           // 4608 u32
#define SMEM_PW (OCCH*9)            // 576  u32
#define SMEM_A  (6*WW*CW)           // 1344 u32
#define SMEM_U32 (SMEM_W + SMEM_PW + SMEM_A)

__global__ void __launch_bounds__(128) conv_kernel(int which) {
    extern __shared__ uint32_t sh[];
    uint32_t* s_w  = sh;
    int*      s_pw = (int*)(sh + SMEM_W);
    uint32_t* s_a  = sh + SMEM_W + SMEM_PW;

    const int n   = blockIdx.y;
    const int h0  = blockIdx.x * TH;
    const int oc0 = blockIdx.z * OCCH;
    const int tid = threadIdx.x;

    const uint32_t* wb = g_wb[which] + oc0*72;
    const int*      pw = g_pw[which] + oc0*9;

    for (int i = tid; i < SMEM_W;  i += 128) s_w[i]  = wb[i];
    for (int i = tid; i < SMEM_PW; i += 128) s_pw[i] = pw[i];
    // activation tile: rows h0-1 .. h0+4 (zero outside image)
    for (int i = tid; i < SMEM_A; i += 128) {
        int rr  = i / (WW*CW);
        int rem = i - rr*(WW*CW);
        int hh  = h0 - 1 + rr;
        s_a[i] = (hh >= 0 && hh < HH) ? g_bits[n*(PIX*CW) + hh*(WW*CW) + rem] : 0u;
    }
    __syncthreads();

    const bool active = (tid < TH*WW);        // 112 workers
    const int p = active ? tid : (TH*WW - 1);
    const int r = p / WW;
    const int w = p - r*WW;
    const int h = h0 + r;

    // per-pixel activation bits in registers (zero for out-of-image columns)
    uint32_t a[72];
    #pragma unroll
    for (int ky = 0; ky < 3; ky++)
        #pragma unroll
        for (int kx = 0; kx < 3; kx++) {
            int ww = w + kx - 1;
            bool v = (ww >= 0) && (ww < WW);
            int base = ((r + ky)*WW + (v ? ww : 0))*CW;
            #pragma unroll
            for (int j = 0; j < CW; j++)
                a[(ky*3+kx)*CW + j] = v ? s_a[base + j] : 0u;
        }

    const int inv_row = (h == 0) ? 0 : ((h == HH-1) ? 2 : -1);
    const int inv_col = (w == 0) ? 0 : ((w == WW-1) ? 2 : -1);
    const int nv = ((inv_row < 0) ? 3 : 2) * ((inv_col < 0) ? 3 : 2);
    const int base256 = CC * nv;

    short* yout = g_y + n*(CC*PIX) + (size_t)oc0*PIX + h0*WW + p; // + oc*PIX per channel
    int* gsum = g_sum[which] + oc0;
    unsigned long long* gsq = g_sq[which] + oc0;
    const int lane = tid & 31;

    const uint32_t* wrow = s_w;
    for (int oc = 0; oc < OCCH; oc++, wrow += 72) {
        int a0 = 0, a1 = 0, a2 = 0, a3 = 0;
        #pragma unroll
        for (int t = 0; t < 18; t++) {
            a0 += __popc(a[t*4+0] ^ wrow[t*4+0]);
            a1 += __popc(a[t*4+1] ^ wrow[t*4+1]);
            a2 += __popc(a[t*4+2] ^ wrow[t*4+2]);
            a3 += __popc(a[t*4+3] ^ wrow[t*4+3]);
        }
        int acc = (a0 + a1) + (a2 + a3);

        int corr = 0;
        const int* pwo = s_pw + oc*9;
        if (inv_row >= 0)
            corr += pwo[inv_row*3+0] + pwo[inv_row*3+1] + pwo[inv_row*3+2];
        if (inv_col >= 0)
            corr += pwo[inv_col] + pwo[3+inv_col] + pwo[6+inv_col];
        if (inv_row >= 0 && inv_col >= 0)
            corr -= pwo[inv_row*3 + inv_col];

        int y = base256 - 2*acc + 2*corr;
        if (!active) y = 0;
        if (active) yout[oc*PIX] = (short)y;

        int s1 = __reduce_add_sync(0xffffffffu, y);
        int s2 = __reduce_add_sync(0xffffffffu, y*y);   // <= 32*2304^2 < 2^31
        if (lane == 0) {
            atomicAdd(&gsum[oc], s1);
            atomicAdd(&gsq[oc], (unsigned long long)(unsigned int)s2);
        }
    }
}

// ---------------- BN statistics -> scale/shift (exact integer sums) -------
__global__ void stats_kernel(int which, const float* __restrict__ gamma,
                             const float* __restrict__ beta) {
    int c = threadIdx.x;                       // 256 threads
    double m   = (double)g_sum[which][c] / (double)NPIX;
    double ex2 = (double)g_sq [which][c] / (double)NPIX;
    double var = ex2 - m*m;
    double inv = rsqrt(var + 1e-5);
    double gs  = (double)gamma[c] * inv;
    g_scale[which][c] = (float)gs;
    g_shift[which][c] = (float)((double)beta[c] - m * gs);
}

// ---------------- BN apply + residual + hardtanh ---------------------------
__global__ void __launch_bounds__(256) bnres_kernel(int which,
                                                    const float* __restrict__ res_in,
                                                    float* __restrict__ dst_out) {
    int idx = blockIdx.x * 256 + threadIdx.x;      // grid sized exactly to TOT
    int c = (idx / PIX) & (CC - 1);
    float v = fmaf((float)g_y[idx], g_scale[which][c], g_shift[which][c]);
    const float* res = (which == 0) ? res_in : g_out1;
    v += res[idx];
    v = fminf(1.0f, fmaxf(-1.0f, v));
    if (which == 0) g_out1[idx] = v;
    else            dst_out[idx] = v;
}

// ---------------- launcher -------------------------------------------------
extern "C" void kernel_launch(void* const* d_in, const int* in_sizes, int n_in,
                              void* d_out, int out_size) {
    const float* x      = (const float*)d_in[0];
    const float* w1     = (const float*)d_in[1];
    const float* gamma1 = (const float*)d_in[2];
    const float* beta1  = (const float*)d_in[3];
    const float* w2     = (const float*)d_in[4];
    const float* gamma2 = (const float*)d_in[5];
    const float* beta2  = (const float*)d_in[6];
    float* out = (float*)d_out;

    constexpr int SMEM_BYTES = SMEM_U32 * 4;       // 26,112 B

    zero_kernel<<<1, 256>>>();
    pack_w_kernel<<<dim3(CC, 2), dim3(32, 9)>>>(w1, w2);

    // stage 1
    pack_sign_kernel<<<dim3(HH, NB), 256>>>(x, 0);
    conv_kernel<<<dim3(HH/TH, NB, NCH), 128, SMEM_BYTES>>>(0);
    stats_kernel<<<1, 256>>>(0, gamma1, beta1);
    bnres_kernel<<<TOT/256, 256>>>(0, x, nullptr);

    // stage 2
    pack_sign_kernel<<<dim3(HH, NB), 256>>>(nullptr, 1);
    conv_kernel<<<dim3(HH/TH, NB, NCH), 128, SMEM_BYTES>>>(1);
    stats_kernel<<<1, 256>>>(1, gamma2, beta2);
    bnres_kernel<<<TOT/256, 256>>>(1, nullptr, out);
}